// round 1
// baseline (speedup 1.0000x reference)
#include <cuda_runtime.h>
#include <math.h>

#define N_NODES 50000
#define N_EDGES 500000
#define NB      64
#define H       128
#define STEPS   3

#define TS 128   // tile rows/cols
#define KC 64    // K chunk

// ---------------- scratch (static device allocations; no cudaMalloc) ----------------
__device__ float g_edge[(size_t)N_EDGES * H];     // updated edge_attr
__device__ float g_x[(size_t)N_NODES * H];        // updated x
__device__ float g_u[NB * H];                     // updated u
__device__ float g_aggSum[(size_t)N_NODES * H];   // per-node edge aggregation sums
__device__ float g_graphSum[NB * H];              // per-graph node sums
__device__ float g_cntE[N_NODES];                 // 1/max(in-degree,1)
__device__ float g_cntB[NB];                      // 1/max(nodes per graph,1)

// ---------------- small utility kernels ----------------
__global__ void k_zero(float* p, int n) {
    int i = blockIdx.x * blockDim.x + threadIdx.x;
    int stride = gridDim.x * blockDim.x;
    for (; i < n; i += stride) p[i] = 0.f;
}

__global__ void k_count(const int* __restrict__ idx, int n, float* cnt) {
    int i = blockIdx.x * blockDim.x + threadIdx.x;
    int stride = gridDim.x * blockDim.x;
    for (; i < n; i += stride) atomicAdd(&cnt[idx[i]], 1.f);
}

__global__ void k_invert(float* c, int n) {
    int i = blockIdx.x * blockDim.x + threadIdx.x;
    if (i < n) c[i] = 1.f / fmaxf(c[i], 1.f);
}

// ---------------- math helpers ----------------
__device__ __forceinline__ float sigm(float x) { return 1.f / (1.f + __expf(-x)); }

// C[128x128] += A_chunk[64x128 in k-major/transposed] * B_chunk[64x128 in k-major]
__device__ __forceinline__ void mma_chunk(const float* __restrict__ aT,
                                          const float* __restrict__ bT,
                                          int tx, int ty, float acc[8][8]) {
#pragma unroll 4
    for (int k = 0; k < KC; k++) {
        float a[8], b[8];
        *(float4*)(a)     = *(const float4*)(aT + k * TS + ty * 8);
        *(float4*)(a + 4) = *(const float4*)(aT + k * TS + ty * 8 + 4);
        *(float4*)(b)     = *(const float4*)(bT + k * TS + tx * 8);
        *(float4*)(b + 4) = *(const float4*)(bT + k * TS + tx * 8 + 4);
#pragma unroll
        for (int i = 0; i < 8; i++)
#pragma unroll
            for (int j = 0; j < 8; j++)
                acc[i][j] = fmaf(a[i], b[j], acc[i][j]);
    }
}

// load 64xK chunk of W^T into smem: sB[k][col] = w[col*ldw + c0 + k]
__device__ __forceinline__ void load_w(float* sB, const float* __restrict__ w,
                                       int ldw, int c0, int tid) {
#pragma unroll
    for (int t = 0; t < 32; t++) {
        int i = tid + t * 256;
        int col = i & 127;
        int kk = i >> 7;
        sB[kk * TS + col] = __ldg(w + col * ldw + c0 + kk);
    }
}

// acc += A(aT, full 128 K) @ W^T  (K=128)
__device__ __forceinline__ void gemm128(const float* aT, const float* __restrict__ w,
                                        int ldw, float* sB, int tid, int tx, int ty,
                                        float acc[8][8]) {
    for (int kc = 0; kc < 2; kc++) {
        load_w(sB, w, ldw, kc * KC, tid);
        __syncthreads();
        mma_chunk(aT + kc * KC * TS, sB, tx, ty, acc);
        __syncthreads();
    }
}

// Shared tail: relu(MLP1 acc) -> MLP2 -> GRU -> write new state + atomic scatter
__device__ __forceinline__ void tail_mlp_gru(
    float acc[8][8],
    const float* __restrict__ b1, const float* __restrict__ w2, const float* __restrict__ b2,
    const float* __restrict__ wih, const float* __restrict__ whh,
    const float* __restrict__ bih, const float* __restrict__ bhh,
    float* __restrict__ outp, float* __restrict__ scatSum, const int* __restrict__ sScat,
    float* sHT, const float* sOldT, float* sB,
    int row0, int nrows, int tid, int tx, int ty)
{
    const int c0 = tx * 8, r0 = ty * 8;
    float bv[8], bv2[8];

    // h1 = relu(acc + b1), stored transposed in sHT
#pragma unroll
    for (int j = 0; j < 8; j++) bv[j] = __ldg(b1 + c0 + j);
#pragma unroll
    for (int i = 0; i < 8; i++)
#pragma unroll
        for (int j = 0; j < 8; j++) {
            float v = acc[i][j] + bv[j];
            sHT[(c0 + j) * TS + r0 + i] = fmaxf(v, 0.f);
        }
    __syncthreads();

    // e_out = h1 @ w2^T + b2
    float g[8][8];
#pragma unroll
    for (int i = 0; i < 8; i++)
#pragma unroll
        for (int j = 0; j < 8; j++) g[i][j] = 0.f;
    gemm128(sHT, w2, H, sB, tid, tx, ty, g);
#pragma unroll
    for (int j = 0; j < 8; j++) bv[j] = __ldg(b2 + c0 + j);
    // gemm128 ended with syncthreads -> safe to overwrite sHT with e_out (transposed)
#pragma unroll
    for (int i = 0; i < 8; i++)
#pragma unroll
        for (int j = 0; j < 8; j++)
            sHT[(c0 + j) * TS + r0 + i] = g[i][j] + bv[j];
    __syncthreads();

    // ---- r gate: sigmoid(ir + hr) ----
    float rn[8][8];
#pragma unroll
    for (int i = 0; i < 8; i++)
#pragma unroll
        for (int j = 0; j < 8; j++) g[i][j] = 0.f;
    gemm128(sHT, wih, H, sB, tid, tx, ty, g);       // ir
    gemm128(sOldT, whh, H, sB, tid, tx, ty, g);     // hr
#pragma unroll
    for (int j = 0; j < 8; j++) { bv[j] = __ldg(bih + c0 + j); bv2[j] = __ldg(bhh + c0 + j); }
#pragma unroll
    for (int i = 0; i < 8; i++)
#pragma unroll
        for (int j = 0; j < 8; j++)
            rn[i][j] = sigm(g[i][j] + bv[j] + bv2[j]);

    // ---- n gate: tanh(ig + r*hg) ----
#pragma unroll
    for (int i = 0; i < 8; i++)
#pragma unroll
        for (int j = 0; j < 8; j++) g[i][j] = 0.f;
    gemm128(sOldT, whh + 2 * H * H, H, sB, tid, tx, ty, g);   // hg
#pragma unroll
    for (int j = 0; j < 8; j++) bv2[j] = __ldg(bhh + 2 * H + c0 + j);
#pragma unroll
    for (int i = 0; i < 8; i++)
#pragma unroll
        for (int j = 0; j < 8; j++)
            g[i][j] = (g[i][j] + bv2[j]) * rn[i][j];
    gemm128(sHT, wih + 2 * H * H, H, sB, tid, tx, ty, g);     // + ig
#pragma unroll
    for (int j = 0; j < 8; j++) bv[j] = __ldg(bih + 2 * H + c0 + j);
#pragma unroll
    for (int i = 0; i < 8; i++)
#pragma unroll
        for (int j = 0; j < 8; j++)
            rn[i][j] = tanhf(g[i][j] + bv[j]);                // n stored in rn

    // ---- z gate + output ----
#pragma unroll
    for (int i = 0; i < 8; i++)
#pragma unroll
        for (int j = 0; j < 8; j++) g[i][j] = 0.f;
    gemm128(sHT, wih + H * H, H, sB, tid, tx, ty, g);         // iz
    gemm128(sOldT, whh + H * H, H, sB, tid, tx, ty, g);       // hz
#pragma unroll
    for (int j = 0; j < 8; j++) { bv[j] = __ldg(bih + H + c0 + j); bv2[j] = __ldg(bhh + H + c0 + j); }

#pragma unroll
    for (int i = 0; i < 8; i++) {
        int gr = row0 + r0 + i;
        if (gr >= nrows) break;
        float h[8];
#pragma unroll
        for (int j = 0; j < 8; j++) {
            float z = sigm(g[i][j] + bv[j] + bv2[j]);
            float hold = sOldT[(c0 + j) * TS + r0 + i];
            h[j] = (1.f - z) * rn[i][j] + z * hold;
        }
        float4* op = (float4*)(outp + (size_t)gr * H + c0);
        op[0] = make_float4(h[0], h[1], h[2], h[3]);
        op[1] = make_float4(h[4], h[5], h[6], h[7]);
        int sidx = sScat[r0 + i];
#pragma unroll
        for (int j = 0; j < 8; j++)
            atomicAdd(scatSum + sidx * H + c0 + j, h[j]);
    }
}

// ---------------- edge model kernel (fused MLP + GRU + scatter) ----------------
extern __shared__ float smem[];

__global__ __launch_bounds__(256) void k_edge(
    const float* __restrict__ x, const float* __restrict__ eain, float* __restrict__ eaout,
    const float* __restrict__ u,
    const int* __restrict__ src, const int* __restrict__ dst, const int* __restrict__ batch,
    const float* __restrict__ w1, const float* __restrict__ b1,
    const float* __restrict__ w2, const float* __restrict__ b2,
    const float* __restrict__ wih, const float* __restrict__ whh,
    const float* __restrict__ bih, const float* __restrict__ bhh,
    float* __restrict__ aggSum, int E)
{
    float* sAT   = smem;                     // 64*128
    float* sB    = sAT + KC * TS;            // 64*128
    float* sHT   = sB + KC * TS;             // 128*128
    float* sOldT = sHT + TS * TS;            // 128*128
    int* sSrc = (int*)(sOldT + TS * TS);
    int* sDst = sSrc + TS;
    int* sBat = sDst + TS;

    const int tid = threadIdx.x, tx = tid & 15, ty = tid >> 4;
    const int row0 = blockIdx.x * TS;

    if (tid < TS) {
        int e = row0 + tid;
        int s = 0, d = 0, bb = 0;
        if (e < E) { s = src[e]; d = dst[e]; bb = batch[s]; }
        sSrc[tid] = s; sDst[tid] = d; sBat[tid] = bb;
    }
    __syncthreads();

    // old edge_attr tile, transposed (k-major)
#pragma unroll 4
    for (int t = 0; t < 64; t++) {
        int i = tid + t * 256;
        int row = i & 127, k = i >> 7;
        float v = 0.f;
        if (row0 + row < E) v = eain[(size_t)(row0 + row) * H + k];
        sOldT[k * TS + row] = v;
    }
    __syncthreads();

    // phase 1: h1_acc = e_in @ w1^T (K = 4H = 512)
    float acc[8][8];
#pragma unroll
    for (int i = 0; i < 8; i++)
#pragma unroll
        for (int j = 0; j < 8; j++) acc[i][j] = 0.f;

    for (int kc = 0; kc < 8; kc++) {
        const float* aPtr;
        if (kc == 4 || kc == 5) {
            aPtr = sOldT + (kc - 4) * KC * TS;   // edge_attr cols come from sOldT
        } else {
            int c0 = kc * KC;
#pragma unroll 4
            for (int t = 0; t < 32; t++) {
                int i = tid + t * 256;
                int row = i & 127, kk = i >> 7;
                int c = c0 + kk;
                float v = 0.f;
                if (row0 + row < E) {
                    if (c < H)           v = x[sSrc[row] * H + c];
                    else if (c < 2 * H)  v = x[sDst[row] * H + (c - H)];
                    else                 v = u[sBat[row] * H + (c - 3 * H)];
                }
                sAT[kk * TS + row] = v;
            }
            aPtr = sAT;
        }
        load_w(sB, w1, 4 * H, kc * KC, tid);
        __syncthreads();
        mma_chunk(aPtr, sB, tx, ty, acc);
        __syncthreads();
    }

    tail_mlp_gru(acc, b1, w2, b2, wih, whh, bih, bhh,
                 eaout, aggSum, sDst, sHT, sOldT, sB, row0, E, tid, tx, ty);
}

// ---------------- node model kernel ----------------
__global__ __launch_bounds__(256) void k_node(
    const float* __restrict__ xin, float* __restrict__ xout,
    const float* __restrict__ u, const int* __restrict__ batch,
    const float* __restrict__ aggSum, const float* __restrict__ invE,
    const float* __restrict__ w1, const float* __restrict__ b1,
    const float* __restrict__ w2, const float* __restrict__ b2,
    const float* __restrict__ wih, const float* __restrict__ whh,
    const float* __restrict__ bih, const float* __restrict__ bhh,
    float* __restrict__ graphSum, int N)
{
    float* sAT   = smem;
    float* sB    = sAT + KC * TS;
    float* sHT   = sB + KC * TS;
    float* sOldT = sHT + TS * TS;
    int*   sBat  = (int*)(sOldT + TS * TS);
    float* sInv  = (float*)(sBat + TS);

    const int tid = threadIdx.x, tx = tid & 15, ty = tid >> 4;
    const int row0 = blockIdx.x * TS;

    if (tid < TS) {
        int n = row0 + tid;
        int bb = 0; float iv = 0.f;
        if (n < N) { bb = batch[n]; iv = invE[n]; }
        sBat[tid] = bb; sInv[tid] = iv;
    }
    __syncthreads();

    // old x tile, transposed
#pragma unroll 4
    for (int t = 0; t < 64; t++) {
        int i = tid + t * 256;
        int row = i & 127, k = i >> 7;
        float v = 0.f;
        if (row0 + row < N) v = xin[(size_t)(row0 + row) * H + k];
        sOldT[k * TS + row] = v;
    }
    __syncthreads();

    float acc[8][8];
#pragma unroll
    for (int i = 0; i < 8; i++)
#pragma unroll
        for (int j = 0; j < 8; j++) acc[i][j] = 0.f;

    // phase 1: n_in @ w1^T (K = 3H = 384)
    for (int kc = 0; kc < 6; kc++) {
        const float* aPtr;
        if (kc < 2) {
            aPtr = sOldT + kc * KC * TS;   // x columns
        } else {
            int c0 = kc * KC;
#pragma unroll 4
            for (int t = 0; t < 32; t++) {
                int i = tid + t * 256;
                int row = i & 127, kk = i >> 7;
                int c = c0 + kk;
                float v = 0.f;
                if (row0 + row < N) {
                    if (c < 2 * H) v = aggSum[(size_t)(row0 + row) * H + (c - H)] * sInv[row];
                    else           v = u[sBat[row] * H + (c - 2 * H)];
                }
                sAT[kk * TS + row] = v;
            }
            aPtr = sAT;
        }
        load_w(sB, w1, 3 * H, kc * KC, tid);
        __syncthreads();
        mma_chunk(aPtr, sB, tx, ty, acc);
        __syncthreads();
    }

    tail_mlp_gru(acc, b1, w2, b2, wih, whh, bih, bhh,
                 xout, graphSum, sBat, sHT, sOldT, sB, row0, N, tid, tx, ty);
}

// ---------------- global model kernel (64 blocks x 128 threads) ----------------
__device__ __forceinline__ float dot128(const float* __restrict__ w, const float* v) {
    float s0 = 0, s1 = 0, s2 = 0, s3 = 0;
#pragma unroll 8
    for (int k = 0; k < H; k += 4) {
        s0 = fmaf(w[k],     v[k],     s0);
        s1 = fmaf(w[k + 1], v[k + 1], s1);
        s2 = fmaf(w[k + 2], v[k + 2], s2);
        s3 = fmaf(w[k + 3], v[k + 3], s3);
    }
    return (s0 + s1) + (s2 + s3);
}

__global__ __launch_bounds__(128) void k_global(
    const float* __restrict__ uin, float* __restrict__ uout,
    const float* __restrict__ graphSum, const float* __restrict__ invB,
    const float* __restrict__ w1, const float* __restrict__ b1,
    const float* __restrict__ w2, const float* __restrict__ b2,
    const float* __restrict__ wih, const float* __restrict__ whh,
    const float* __restrict__ bih, const float* __restrict__ bhh,
    float* __restrict__ out, int step)
{
    __shared__ float gin[2 * H];
    __shared__ float h1[H];
    __shared__ float eo[H];
    int b = blockIdx.x, t = threadIdx.x;
    float uold = uin[b * H + t];
    gin[t] = uold;
    gin[H + t] = graphSum[b * H + t] * invB[b];
    __syncthreads();

    // h1 = relu(g_in @ w1^T + b1), K = 2H
    {
        float s0 = 0, s1 = 0, s2 = 0, s3 = 0;
        const float* wr = w1 + t * 2 * H;
#pragma unroll 8
        for (int k = 0; k < 2 * H; k += 4) {
            s0 = fmaf(wr[k],     gin[k],     s0);
            s1 = fmaf(wr[k + 1], gin[k + 1], s1);
            s2 = fmaf(wr[k + 2], gin[k + 2], s2);
            s3 = fmaf(wr[k + 3], gin[k + 3], s3);
        }
        float h = (s0 + s1) + (s2 + s3) + b1[t];
        h1[t] = fmaxf(h, 0.f);
    }
    __syncthreads();

    eo[t] = dot128(w2 + t * H, h1) + b2[t];
    __syncthreads();

    float ir = dot128(wih + t * H,           eo)  + bih[t];
    float hr = dot128(whh + t * H,           gin) + bhh[t];
    float iz = dot128(wih + (H + t) * H,     eo)  + bih[H + t];
    float hz = dot128(whh + (H + t) * H,     gin) + bhh[H + t];
    float ig = dot128(wih + (2 * H + t) * H, eo)  + bih[2 * H + t];
    float hg = dot128(whh + (2 * H + t) * H, gin) + bhh[2 * H + t];

    float r = sigm(ir + hr);
    float z = sigm(iz + hz);
    float n = tanhf(ig + r * hg);
    float hn = (1.f - z) * n + z * uold;
    uout[b * H + t] = hn;
    out[(b * STEPS + step) * H + t] = hn;
}

// ---------------- launch ----------------
extern "C" void kernel_launch(void* const* d_in, const int* in_sizes, int n_in,
                              void* d_out, int out_size) {
    const float* x        = (const float*)d_in[0];
    const int*   ei       = (const int*)d_in[1];
    const float* ea       = (const float*)d_in[2];
    const float* u        = (const float*)d_in[3];
    const int*   batch    = (const int*)d_in[4];
    const float* edge_w1  = (const float*)d_in[5];
    const float* edge_b1  = (const float*)d_in[6];
    const float* edge_w2  = (const float*)d_in[7];
    const float* edge_b2  = (const float*)d_in[8];
    const float* node_w1  = (const float*)d_in[9];
    const float* node_b1  = (const float*)d_in[10];
    const float* node_w2  = (const float*)d_in[11];
    const float* node_b2  = (const float*)d_in[12];
    const float* glob_w1  = (const float*)d_in[13];
    const float* glob_b1  = (const float*)d_in[14];
    const float* glob_w2  = (const float*)d_in[15];
    const float* glob_b2  = (const float*)d_in[16];
    const float* egru_wih = (const float*)d_in[17];
    const float* egru_whh = (const float*)d_in[18];
    const float* egru_bih = (const float*)d_in[19];
    const float* egru_bhh = (const float*)d_in[20];
    const float* ngru_wih = (const float*)d_in[21];
    const float* ngru_whh = (const float*)d_in[22];
    const float* ngru_bih = (const float*)d_in[23];
    const float* ngru_bhh = (const float*)d_in[24];
    const float* ggru_wih = (const float*)d_in[25];
    const float* ggru_whh = (const float*)d_in[26];
    const float* ggru_bih = (const float*)d_in[27];
    const float* ggru_bhh = (const float*)d_in[28];
    float* out = (float*)d_out;

    const int E = in_sizes[1] / 2;
    const int N = in_sizes[0] / H;
    const int B = in_sizes[3] / H;

    float *edgeBuf, *xBuf, *uBuf, *aggSum, *graphSum, *cntE, *cntB;
    cudaGetSymbolAddress((void**)&edgeBuf,  g_edge);
    cudaGetSymbolAddress((void**)&xBuf,     g_x);
    cudaGetSymbolAddress((void**)&uBuf,     g_u);
    cudaGetSymbolAddress((void**)&aggSum,   g_aggSum);
    cudaGetSymbolAddress((void**)&graphSum, g_graphSum);
    cudaGetSymbolAddress((void**)&cntE,     g_cntE);
    cudaGetSymbolAddress((void**)&cntB,     g_cntB);

    const int* src = ei;
    const int* dst = ei + E;

    const int smemBytes = (2 * KC * TS + 2 * TS * TS) * 4 + 4 * TS * 4;  // 198656 B
    cudaFuncSetAttribute(k_edge, cudaFuncAttributeMaxDynamicSharedMemorySize, smemBytes);
    cudaFuncSetAttribute(k_node, cudaFuncAttributeMaxDynamicSharedMemorySize, smemBytes);

    // segment counts (degree is launch-invariant; recomputed each call for determinism)
    k_zero<<<(N + 255) / 256, 256>>>(cntE, N);
    k_zero<<<1, 64>>>(cntB, B);
    k_count<<<512, 256>>>(dst, E, cntE);
    k_count<<<128, 256>>>(batch, N, cntB);
    k_invert<<<(N + 255) / 256, 256>>>(cntE, N);
    k_invert<<<1, 64>>>(cntB, B);

    for (int step = 0; step < STEPS; step++) {
        k_zero<<<4096, 256>>>(aggSum, N * H);
        k_zero<<<32, 256>>>(graphSum, B * H);

        const float* xin  = (step == 0) ? x  : xBuf;
        const float* eain = (step == 0) ? ea : edgeBuf;
        const float* uin  = (step == 0) ? u  : uBuf;

        k_edge<<<(E + TS - 1) / TS, 256, smemBytes>>>(
            xin, eain, edgeBuf, uin, src, dst, batch,
            edge_w1, edge_b1, edge_w2, edge_b2,
            egru_wih, egru_whh, egru_bih, egru_bhh,
            aggSum, E);

        k_node<<<(N + TS - 1) / TS, 256, smemBytes>>>(
            xin, xBuf, uin, batch, aggSum, cntE,
            node_w1, node_b1, node_w2, node_b2,
            ngru_wih, ngru_whh, ngru_bih, ngru_bhh,
            graphSum, N);

        k_global<<<B, H>>>(
            uin, uBuf, graphSum, cntB,
            glob_w1, glob_b1, glob_w2, glob_b2,
            ggru_wih, ggru_whh, ggru_bih, ggru_bhh,
            out, step);
    }
}

// round 2
// speedup vs baseline: 1.0015x; 1.0015x over previous
#include <cuda_runtime.h>
#include <math.h>

#define N_NODES 50000
#define N_EDGES 500000
#define NB      64
#define H       128
#define STEPS   3

#define TS 128   // tile rows/cols
#define KC 64    // K chunk

// ---------------- scratch (static device allocations; no cudaMalloc) ----------------
__device__ float g_edge[(size_t)N_EDGES * H];     // updated edge_attr
__device__ float g_x[(size_t)N_NODES * H];        // updated x
__device__ float g_u[NB * H];                     // updated u
__device__ float g_aggSum[(size_t)N_NODES * H];   // per-node edge aggregation sums
__device__ float g_graphSum[NB * H];              // per-graph node sums
__device__ float g_cntE[N_NODES];                 // 1/max(in-degree,1)
__device__ float g_cntB[NB];                      // 1/max(nodes per graph,1)

// ---------------- small utility kernels ----------------
__global__ void k_zero(float* p, int n) {
    int i = blockIdx.x * blockDim.x + threadIdx.x;
    int stride = gridDim.x * blockDim.x;
    for (; i < n; i += stride) p[i] = 0.f;
}

__global__ void k_count(const int* __restrict__ idx, int n, float* cnt) {
    int i = blockIdx.x * blockDim.x + threadIdx.x;
    int stride = gridDim.x * blockDim.x;
    for (; i < n; i += stride) atomicAdd(&cnt[idx[i]], 1.f);
}

__global__ void k_invert(float* c, int n) {
    int i = blockIdx.x * blockDim.x + threadIdx.x;
    if (i < n) c[i] = 1.f / fmaxf(c[i], 1.f);
}

// ---------------- math helpers ----------------
__device__ __forceinline__ float sigm(float x) { return 1.f / (1.f + __expf(-x)); }

// C[128x128] += A_chunk[64x128 in k-major/transposed] * B_chunk[64x128 in k-major]
__device__ __forceinline__ void mma_chunk(const float* __restrict__ aT,
                                          const float* __restrict__ bT,
                                          int tx, int ty, float acc[8][8]) {
#pragma unroll 4
    for (int k = 0; k < KC; k++) {
        float a[8], b[8];
        *(float4*)(a)     = *(const float4*)(aT + k * TS + ty * 8);
        *(float4*)(a + 4) = *(const float4*)(aT + k * TS + ty * 8 + 4);
        *(float4*)(b)     = *(const float4*)(bT + k * TS + tx * 8);
        *(float4*)(b + 4) = *(const float4*)(bT + k * TS + tx * 8 + 4);
#pragma unroll
        for (int i = 0; i < 8; i++)
#pragma unroll
            for (int j = 0; j < 8; j++)
                acc[i][j] = fmaf(a[i], b[j], acc[i][j]);
    }
}

// load 64xK chunk of W^T into smem: sB[k][col] = w[col*ldw + c0 + k]
__device__ __forceinline__ void load_w(float* sB, const float* __restrict__ w,
                                       int ldw, int c0, int tid) {
#pragma unroll
    for (int t = 0; t < 32; t++) {
        int i = tid + t * 256;
        int col = i & 127;
        int kk = i >> 7;
        sB[kk * TS + col] = __ldg(w + col * ldw + c0 + kk);
    }
}

// acc += A(aT, full 128 K) @ W^T  (K=128)
__device__ __forceinline__ void gemm128(const float* aT, const float* __restrict__ w,
                                        int ldw, float* sB, int tid, int tx, int ty,
                                        float acc[8][8]) {
    for (int kc = 0; kc < 2; kc++) {
        load_w(sB, w, ldw, kc * KC, tid);
        __syncthreads();
        mma_chunk(aT + kc * KC * TS, sB, tx, ty, acc);
        __syncthreads();
    }
}

// Shared tail: relu(MLP1 acc) -> MLP2 -> GRU -> write new state + atomic scatter
__device__ __forceinline__ void tail_mlp_gru(
    float acc[8][8],
    const float* __restrict__ b1, const float* __restrict__ w2, const float* __restrict__ b2,
    const float* __restrict__ wih, const float* __restrict__ whh,
    const float* __restrict__ bih, const float* __restrict__ bhh,
    float* __restrict__ outp, float* __restrict__ scatSum, const int* __restrict__ sScat,
    float* sHT, const float* sOldT, float* sB,
    int row0, int nrows, int tid, int tx, int ty)
{
    const int c0 = tx * 8, r0 = ty * 8;
    float bv[8], bv2[8];

    // h1 = relu(acc + b1), stored transposed in sHT
#pragma unroll
    for (int j = 0; j < 8; j++) bv[j] = __ldg(b1 + c0 + j);
#pragma unroll
    for (int i = 0; i < 8; i++)
#pragma unroll
        for (int j = 0; j < 8; j++) {
            float v = acc[i][j] + bv[j];
            sHT[(c0 + j) * TS + r0 + i] = fmaxf(v, 0.f);
        }
    __syncthreads();

    // e_out = h1 @ w2^T + b2
    float g[8][8];
#pragma unroll
    for (int i = 0; i < 8; i++)
#pragma unroll
        for (int j = 0; j < 8; j++) g[i][j] = 0.f;
    gemm128(sHT, w2, H, sB, tid, tx, ty, g);
#pragma unroll
    for (int j = 0; j < 8; j++) bv[j] = __ldg(b2 + c0 + j);
    // gemm128 ended with syncthreads -> safe to overwrite sHT with e_out (transposed)
#pragma unroll
    for (int i = 0; i < 8; i++)
#pragma unroll
        for (int j = 0; j < 8; j++)
            sHT[(c0 + j) * TS + r0 + i] = g[i][j] + bv[j];
    __syncthreads();

    // ---- r gate: sigmoid(ir + hr) ----
    float rn[8][8];
#pragma unroll
    for (int i = 0; i < 8; i++)
#pragma unroll
        for (int j = 0; j < 8; j++) g[i][j] = 0.f;
    gemm128(sHT, wih, H, sB, tid, tx, ty, g);       // ir
    gemm128(sOldT, whh, H, sB, tid, tx, ty, g);     // hr
#pragma unroll
    for (int j = 0; j < 8; j++) { bv[j] = __ldg(bih + c0 + j); bv2[j] = __ldg(bhh + c0 + j); }
#pragma unroll
    for (int i = 0; i < 8; i++)
#pragma unroll
        for (int j = 0; j < 8; j++)
            rn[i][j] = sigm(g[i][j] + bv[j] + bv2[j]);

    // ---- n gate: tanh(ig + r*hg) ----
#pragma unroll
    for (int i = 0; i < 8; i++)
#pragma unroll
        for (int j = 0; j < 8; j++) g[i][j] = 0.f;
    gemm128(sOldT, whh + 2 * H * H, H, sB, tid, tx, ty, g);   // hg
#pragma unroll
    for (int j = 0; j < 8; j++) bv2[j] = __ldg(bhh + 2 * H + c0 + j);
#pragma unroll
    for (int i = 0; i < 8; i++)
#pragma unroll
        for (int j = 0; j < 8; j++)
            g[i][j] = (g[i][j] + bv2[j]) * rn[i][j];
    gemm128(sHT, wih + 2 * H * H, H, sB, tid, tx, ty, g);     // + ig
#pragma unroll
    for (int j = 0; j < 8; j++) bv[j] = __ldg(bih + 2 * H + c0 + j);
#pragma unroll
    for (int i = 0; i < 8; i++)
#pragma unroll
        for (int j = 0; j < 8; j++)
            rn[i][j] = tanhf(g[i][j] + bv[j]);                // n stored in rn

    // ---- z gate + output ----
#pragma unroll
    for (int i = 0; i < 8; i++)
#pragma unroll
        for (int j = 0; j < 8; j++) g[i][j] = 0.f;
    gemm128(sHT, wih + H * H, H, sB, tid, tx, ty, g);         // iz
    gemm128(sOldT, whh + H * H, H, sB, tid, tx, ty, g);       // hz
#pragma unroll
    for (int j = 0; j < 8; j++) { bv[j] = __ldg(bih + H + c0 + j); bv2[j] = __ldg(bhh + H + c0 + j); }

#pragma unroll
    for (int i = 0; i < 8; i++) {
        int gr = row0 + r0 + i;
        if (gr >= nrows) break;
        float h[8];
#pragma unroll
        for (int j = 0; j < 8; j++) {
            float z = sigm(g[i][j] + bv[j] + bv2[j]);
            float hold = sOldT[(c0 + j) * TS + r0 + i];
            h[j] = (1.f - z) * rn[i][j] + z * hold;
        }
        float4* op = (float4*)(outp + (size_t)gr * H + c0);
        op[0] = make_float4(h[0], h[1], h[2], h[3]);
        op[1] = make_float4(h[4], h[5], h[6], h[7]);
        int sidx = sScat[r0 + i];
#pragma unroll
        for (int j = 0; j < 8; j++)
            atomicAdd(scatSum + sidx * H + c0 + j, h[j]);
    }
}

// ---------------- edge model kernel (fused MLP + GRU + scatter) ----------------
extern __shared__ float smem[];

__global__ __launch_bounds__(256) void k_edge(
    const float* __restrict__ x, const float* __restrict__ eain, float* __restrict__ eaout,
    const float* __restrict__ u,
    const int* __restrict__ src, const int* __restrict__ dst, const int* __restrict__ batch,
    const float* __restrict__ w1, const float* __restrict__ b1,
    const float* __restrict__ w2, const float* __restrict__ b2,
    const float* __restrict__ wih, const float* __restrict__ whh,
    const float* __restrict__ bih, const float* __restrict__ bhh,
    float* __restrict__ aggSum, int E)
{
    float* sAT   = smem;                     // 64*128
    float* sB    = sAT + KC * TS;            // 64*128
    float* sHT   = sB + KC * TS;             // 128*128
    float* sOldT = sHT + TS * TS;            // 128*128
    int* sSrc = (int*)(sOldT + TS * TS);
    int* sDst = sSrc + TS;
    int* sBat = sDst + TS;

    const int tid = threadIdx.x, tx = tid & 15, ty = tid >> 4;
    const int row0 = blockIdx.x * TS;

    if (tid < TS) {
        int e = row0 + tid;
        int s = 0, d = 0, bb = 0;
        if (e < E) { s = src[e]; d = dst[e]; bb = batch[s]; }
        sSrc[tid] = s; sDst[tid] = d; sBat[tid] = bb;
    }
    __syncthreads();

    // old edge_attr tile, transposed (k-major)
#pragma unroll 4
    for (int t = 0; t < 64; t++) {
        int i = tid + t * 256;
        int row = i & 127, k = i >> 7;
        float v = 0.f;
        if (row0 + row < E) v = eain[(size_t)(row0 + row) * H + k];
        sOldT[k * TS + row] = v;
    }
    __syncthreads();

    // phase 1: h1_acc = e_in @ w1^T (K = 4H = 512)
    float acc[8][8];
#pragma unroll
    for (int i = 0; i < 8; i++)
#pragma unroll
        for (int j = 0; j < 8; j++) acc[i][j] = 0.f;

    for (int kc = 0; kc < 8; kc++) {
        const float* aPtr;
        if (kc == 4 || kc == 5) {
            aPtr = sOldT + (kc - 4) * KC * TS;   // edge_attr cols come from sOldT
        } else {
            int c0 = kc * KC;
#pragma unroll 4
            for (int t = 0; t < 32; t++) {
                int i = tid + t * 256;
                int row = i & 127, kk = i >> 7;
                int c = c0 + kk;
                float v = 0.f;
                if (row0 + row < E) {
                    if (c < H)           v = x[sSrc[row] * H + c];
                    else if (c < 2 * H)  v = x[sDst[row] * H + (c - H)];
                    else                 v = u[sBat[row] * H + (c - 3 * H)];
                }
                sAT[kk * TS + row] = v;
            }
            aPtr = sAT;
        }
        load_w(sB, w1, 4 * H, kc * KC, tid);
        __syncthreads();
        mma_chunk(aPtr, sB, tx, ty, acc);
        __syncthreads();
    }

    tail_mlp_gru(acc, b1, w2, b2, wih, whh, bih, bhh,
                 eaout, aggSum, sDst, sHT, sOldT, sB, row0, E, tid, tx, ty);
}

// ---------------- node model kernel ----------------
__global__ __launch_bounds__(256) void k_node(
    const float* __restrict__ xin, float* __restrict__ xout,
    const float* __restrict__ u, const int* __restrict__ batch,
    const float* __restrict__ aggSum, const float* __restrict__ invE,
    const float* __restrict__ w1, const float* __restrict__ b1,
    const float* __restrict__ w2, const float* __restrict__ b2,
    const float* __restrict__ wih, const float* __restrict__ whh,
    const float* __restrict__ bih, const float* __restrict__ bhh,
    float* __restrict__ graphSum, int N)
{
    float* sAT   = smem;
    float* sB    = sAT + KC * TS;
    float* sHT   = sB + KC * TS;
    float* sOldT = sHT + TS * TS;
    int*   sBat  = (int*)(sOldT + TS * TS);
    float* sInv  = (float*)(sBat + TS);

    const int tid = threadIdx.x, tx = tid & 15, ty = tid >> 4;
    const int row0 = blockIdx.x * TS;

    if (tid < TS) {
        int n = row0 + tid;
        int bb = 0; float iv = 0.f;
        if (n < N) { bb = batch[n]; iv = invE[n]; }
        sBat[tid] = bb; sInv[tid] = iv;
    }
    __syncthreads();

    // old x tile, transposed
#pragma unroll 4
    for (int t = 0; t < 64; t++) {
        int i = tid + t * 256;
        int row = i & 127, k = i >> 7;
        float v = 0.f;
        if (row0 + row < N) v = xin[(size_t)(row0 + row) * H + k];
        sOldT[k * TS + row] = v;
    }
    __syncthreads();

    float acc[8][8];
#pragma unroll
    for (int i = 0; i < 8; i++)
#pragma unroll
        for (int j = 0; j < 8; j++) acc[i][j] = 0.f;

    // phase 1: n_in @ w1^T (K = 3H = 384)
    for (int kc = 0; kc < 6; kc++) {
        const float* aPtr;
        if (kc < 2) {
            aPtr = sOldT + kc * KC * TS;   // x columns
        } else {
            int c0 = kc * KC;
#pragma unroll 4
            for (int t = 0; t < 32; t++) {
                int i = tid + t * 256;
                int row = i & 127, kk = i >> 7;
                int c = c0 + kk;
                float v = 0.f;
                if (row0 + row < N) {
                    if (c < 2 * H) v = aggSum[(size_t)(row0 + row) * H + (c - H)] * sInv[row];
                    else           v = u[sBat[row] * H + (c - 2 * H)];
                }
                sAT[kk * TS + row] = v;
            }
            aPtr = sAT;
        }
        load_w(sB, w1, 3 * H, kc * KC, tid);
        __syncthreads();
        mma_chunk(aPtr, sB, tx, ty, acc);
        __syncthreads();
    }

    tail_mlp_gru(acc, b1, w2, b2, wih, whh, bih, bhh,
                 xout, graphSum, sBat, sHT, sOldT, sB, row0, N, tid, tx, ty);
}

// ---------------- global model kernel (64 blocks x 128 threads) ----------------
__device__ __forceinline__ float dot128(const float* __restrict__ w, const float* v) {
    float s0 = 0, s1 = 0, s2 = 0, s3 = 0;
#pragma unroll 8
    for (int k = 0; k < H; k += 4) {
        s0 = fmaf(w[k],     v[k],     s0);
        s1 = fmaf(w[k + 1], v[k + 1], s1);
        s2 = fmaf(w[k + 2], v[k + 2], s2);
        s3 = fmaf(w[k + 3], v[k + 3], s3);
    }
    return (s0 + s1) + (s2 + s3);
}

__global__ __launch_bounds__(128) void k_global(
    const float* __restrict__ uin, float* __restrict__ uout,
    const float* __restrict__ graphSum, const float* __restrict__ invB,
    const float* __restrict__ w1, const float* __restrict__ b1,
    const float* __restrict__ w2, const float* __restrict__ b2,
    const float* __restrict__ wih, const float* __restrict__ whh,
    const float* __restrict__ bih, const float* __restrict__ bhh,
    float* __restrict__ out, int step)
{
    __shared__ float gin[2 * H];
    __shared__ float h1[H];
    __shared__ float eo[H];
    int b = blockIdx.x, t = threadIdx.x;
    float uold = uin[b * H + t];
    gin[t] = uold;
    gin[H + t] = graphSum[b * H + t] * invB[b];
    __syncthreads();

    // h1 = relu(g_in @ w1^T + b1), K = 2H
    {
        float s0 = 0, s1 = 0, s2 = 0, s3 = 0;
        const float* wr = w1 + t * 2 * H;
#pragma unroll 8
        for (int k = 0; k < 2 * H; k += 4) {
            s0 = fmaf(wr[k],     gin[k],     s0);
            s1 = fmaf(wr[k + 1], gin[k + 1], s1);
            s2 = fmaf(wr[k + 2], gin[k + 2], s2);
            s3 = fmaf(wr[k + 3], gin[k + 3], s3);
        }
        float h = (s0 + s1) + (s2 + s3) + b1[t];
        h1[t] = fmaxf(h, 0.f);
    }
    __syncthreads();

    eo[t] = dot128(w2 + t * H, h1) + b2[t];
    __syncthreads();

    float ir = dot128(wih + t * H,           eo)  + bih[t];
    float hr = dot128(whh + t * H,           gin) + bhh[t];
    float iz = dot128(wih + (H + t) * H,     eo)  + bih[H + t];
    float hz = dot128(whh + (H + t) * H,     gin) + bhh[H + t];
    float ig = dot128(wih + (2 * H + t) * H, eo)  + bih[2 * H + t];
    float hg = dot128(whh + (2 * H + t) * H, gin) + bhh[2 * H + t];

    float r = sigm(ir + hr);
    float z = sigm(iz + hz);
    float n = tanhf(ig + r * hg);
    float hn = (1.f - z) * n + z * uold;
    uout[b * H + t] = hn;
    out[(b * STEPS + step) * H + t] = hn;
}

// ---------------- launch ----------------
extern "C" void kernel_launch(void* const* d_in, const int* in_sizes, int n_in,
                              void* d_out, int out_size) {
    const float* x        = (const float*)d_in[0];
    const int*   ei       = (const int*)d_in[1];
    const float* ea       = (const float*)d_in[2];
    const float* u        = (const float*)d_in[3];
    const int*   batch    = (const int*)d_in[4];
    const float* edge_w1  = (const float*)d_in[5];
    const float* edge_b1  = (const float*)d_in[6];
    const float* edge_w2  = (const float*)d_in[7];
    const float* edge_b2  = (const float*)d_in[8];
    const float* node_w1  = (const float*)d_in[9];
    const float* node_b1  = (const float*)d_in[10];
    const float* node_w2  = (const float*)d_in[11];
    const float* node_b2  = (const float*)d_in[12];
    const float* glob_w1  = (const float*)d_in[13];
    const float* glob_b1  = (const float*)d_in[14];
    const float* glob_w2  = (const float*)d_in[15];
    const float* glob_b2  = (const float*)d_in[16];
    const float* egru_wih = (const float*)d_in[17];
    const float* egru_whh = (const float*)d_in[18];
    const float* egru_bih = (const float*)d_in[19];
    const float* egru_bhh = (const float*)d_in[20];
    const float* ngru_wih = (const float*)d_in[21];
    const float* ngru_whh = (const float*)d_in[22];
    const float* ngru_bih = (const float*)d_in[23];
    const float* ngru_bhh = (const float*)d_in[24];
    const float* ggru_wih = (const float*)d_in[25];
    const float* ggru_whh = (const float*)d_in[26];
    const float* ggru_bih = (const float*)d_in[27];
    const float* ggru_bhh = (const float*)d_in[28];
    float* out = (float*)d_out;

    const int E = in_sizes[1] / 2;
    const int N = in_sizes[0] / H;
    const int B = in_sizes[3] / H;

    float *edgeBuf, *xBuf, *uBuf, *aggSum, *graphSum, *cntE, *cntB;
    cudaGetSymbolAddress((void**)&edgeBuf,  g_edge);
    cudaGetSymbolAddress((void**)&xBuf,     g_x);
    cudaGetSymbolAddress((void**)&uBuf,     g_u);
    cudaGetSymbolAddress((void**)&aggSum,   g_aggSum);
    cudaGetSymbolAddress((void**)&graphSum, g_graphSum);
    cudaGetSymbolAddress((void**)&cntE,     g_cntE);
    cudaGetSymbolAddress((void**)&cntB,     g_cntB);

    const int* src = ei;
    const int* dst = ei + E;

    const int smemBytes = (2 * KC * TS + 2 * TS * TS) * 4 + 4 * TS * 4;  // 198656 B
    cudaFuncSetAttribute(k_edge, cudaFuncAttributeMaxDynamicSharedMemorySize, smemBytes);
    cudaFuncSetAttribute(k_node, cudaFuncAttributeMaxDynamicSharedMemorySize, smemBytes);

    // segment counts (degree is launch-invariant; recomputed each call for determinism)
    k_zero<<<(N + 255) / 256, 256>>>(cntE, N);
    k_zero<<<1, 64>>>(cntB, B);
    k_count<<<512, 256>>>(dst, E, cntE);
    k_count<<<128, 256>>>(batch, N, cntB);
    k_invert<<<(N + 255) / 256, 256>>>(cntE, N);
    k_invert<<<1, 64>>>(cntB, B);

    for (int step = 0; step < STEPS; step++) {
        k_zero<<<4096, 256>>>(aggSum, N * H);
        k_zero<<<32, 256>>>(graphSum, B * H);

        const float* xin  = (step == 0) ? x  : xBuf;
        const float* eain = (step == 0) ? ea : edgeBuf;
        const float* uin  = (step == 0) ? u  : uBuf;

        k_edge<<<(E + TS - 1) / TS, 256, smemBytes>>>(
            xin, eain, edgeBuf, uin, src, dst, batch,
            edge_w1, edge_b1, edge_w2, edge_b2,
            egru_wih, egru_whh, egru_bih, egru_bhh,
            aggSum, E);

        k_node<<<(N + TS - 1) / TS, 256, smemBytes>>>(
            xin, xBuf, uin, batch, aggSum, cntE,
            node_w1, node_b1, node_w2, node_b2,
            ngru_wih, ngru_whh, ngru_bih, ngru_bhh,
            graphSum, N);

        k_global<<<B, H>>>(
            uin, uBuf, graphSum, cntB,
            glob_w1, glob_b1, glob_w2, glob_b2,
            ggru_wih, ggru_whh, ggru_bih, ggru_bhh,
            out, step);
    }
}

// round 4
// speedup vs baseline: 3.1588x; 3.1540x over previous
#include <cuda_runtime.h>
#include <cuda_bf16.h>
#include <math.h>
#include <stdint.h>

#define N_NODES 50000
#define N_EDGES 500000
#define NB      64
#define H       128
#define STEPS   3

#define ASTRIDE 136              // bf16 elements per row (128 + 8 pad)
#define ROWB    272              // bytes per row
#define ARR     34816            // bytes per 128x136 bf16 array
#define LOOFF   34816            // hi->lo offset

// SMEM byte offsets
#define OFF_A    0
#define OFF_OLD  (2 * ARR)
#define OFF_B    (4 * ARR)
#define OFF_IDX  (6 * ARR)
#define SMEM_BYTES (OFF_IDX + 2048)

// ---------------- scratch ----------------
__device__ float g_edge[(size_t)N_EDGES * H];
__device__ float g_x[(size_t)N_NODES * H];
__device__ float g_u[NB * H];
__device__ float g_aggSum[(size_t)N_NODES * H];
__device__ float g_graphSum[NB * H];
__device__ float g_cntE[N_NODES];
__device__ float g_cntB[NB];
__device__ __nv_bfloat16 g_wimg_hi[21 * 128 * ASTRIDE];
__device__ __nv_bfloat16 g_wimg_lo[21 * 128 * ASTRIDE];

// ---------------- helpers ----------------
__device__ __forceinline__ uint32_t smem_u32(const void* p) {
    uint32_t a;
    asm("{ .reg .u64 t; cvta.to.shared.u64 t, %1; cvt.u32.u64 %0, t; }" : "=r"(a) : "l"(p));
    return a;
}
__device__ __forceinline__ void lda4(uint32_t addr, uint32_t r[4]) {
    asm volatile("ldmatrix.sync.aligned.m8n8.x4.shared.b16 {%0,%1,%2,%3}, [%4];"
                 : "=r"(r[0]), "=r"(r[1]), "=r"(r[2]), "=r"(r[3]) : "r"(addr));
}
__device__ __forceinline__ void ldb2(uint32_t addr, uint32_t r[2]) {
    asm volatile("ldmatrix.sync.aligned.m8n8.x2.shared.b16 {%0,%1}, [%2];"
                 : "=r"(r[0]), "=r"(r[1]) : "r"(addr));
}
__device__ __forceinline__ void mma16816(float c[4], const uint32_t a[4], const uint32_t b[2]) {
    asm volatile("mma.sync.aligned.m16n8k16.row.col.f32.bf16.bf16.f32 "
                 "{%0,%1,%2,%3}, {%4,%5,%6,%7}, {%8,%9}, {%0,%1,%2,%3};"
                 : "+f"(c[0]), "+f"(c[1]), "+f"(c[2]), "+f"(c[3])
                 : "r"(a[0]), "r"(a[1]), "r"(a[2]), "r"(a[3]), "r"(b[0]), "r"(b[1]));
}
__device__ __forceinline__ void split_pair(float v0, float v1, uint32_t& wh, uint32_t& wl) {
    __nv_bfloat16 h0 = __float2bfloat16(v0), h1 = __float2bfloat16(v1);
    union { __nv_bfloat162 v; uint32_t u; } a, b;
    a.v = __halves2bfloat162(h0, h1);
    b.v = __halves2bfloat162(__float2bfloat16(v0 - __bfloat162float(h0)),
                             __float2bfloat16(v1 - __bfloat162float(h1)));
    wh = a.u; wl = b.u;
}
__device__ __forceinline__ float sigm(float x) { return 1.f / (1.f + __expf(-x)); }
__device__ __forceinline__ float ftanh(float x) { float y; asm("tanh.approx.f32 %0, %1;" : "=f"(y) : "f"(x)); return y; }

// 3-term split GEMM: acc += A(128rows x128k) @ W^T  using hi/lo bf16 smem images.
// aHi/bHi are smem byte addrs already offset to this warp's mrow / ncol.
__device__ __forceinline__ void gemm128(uint32_t aHi, uint32_t bHi, float acc[2][8][4], int lane) {
    const uint32_t aBase = aHi + (uint32_t)(lane & 15) * ROWB + (uint32_t)(lane >> 4) * 16;
    const uint32_t bBase = bHi + (uint32_t)(lane & 7) * ROWB + (uint32_t)((lane >> 3) & 1) * 16;
#pragma unroll
    for (int ks = 0; ks < 8; ks++) {
        uint32_t kb = ks * 32;
        uint32_t ah0[4], ah1[4], al0[4], al1[4];
        lda4(aBase + kb, ah0);
        lda4(aBase + kb + 16 * ROWB, ah1);
        lda4(aBase + kb + LOOFF, al0);
        lda4(aBase + kb + LOOFF + 16 * ROWB, al1);
#pragma unroll
        for (int j = 0; j < 8; j++) {
            uint32_t ba = bBase + (uint32_t)j * 8 * ROWB + kb;
            uint32_t bh[2], bl[2];
            ldb2(ba, bh);
            ldb2(ba + LOOFF, bl);
            mma16816(acc[0][j], ah0, bh);
            mma16816(acc[1][j], ah1, bh);
            mma16816(acc[0][j], ah0, bl);
            mma16816(acc[1][j], ah1, bl);
            mma16816(acc[0][j], al0, bh);
            mma16816(acc[1][j], al1, bh);
        }
    }
}

#define ZACC(acc) { _Pragma("unroll") for (int i = 0; i < 2; i++) _Pragma("unroll") for (int j = 0; j < 8; j++) _Pragma("unroll") for (int q = 0; q < 4; q++) acc[i][j][q] = 0.f; }

// ---------------- fills ----------------
__device__ __forceinline__ void fill_gather(char* smc, int off, const float* __restrict__ src,
                                            const int* sIdx, int tid) {
#pragma unroll 4
    for (int j = 0; j < 32; j++) {
        int p = tid + j * 256;
        int row = p >> 6, cp = (p & 63) * 2;
        float2 v = *(const float2*)(src + (size_t)sIdx[row] * H + cp);
        uint32_t wh, wl; split_pair(v.x, v.y, wh, wl);
        uint32_t b = (uint32_t)row * ROWB + cp * 2;
        *(uint32_t*)(smc + off + b) = wh;
        *(uint32_t*)(smc + off + LOOFF + b) = wl;
    }
}
__device__ __forceinline__ void fill_direct(char* smc, int off, const float* __restrict__ src,
                                            int tid, int row0, int nrows, const float* sScale) {
#pragma unroll 4
    for (int j = 0; j < 32; j++) {
        int p = tid + j * 256;
        int row = p >> 6, cp = (p & 63) * 2;
        float2 v = make_float2(0.f, 0.f);
        if (row0 + row < nrows) v = *(const float2*)(src + (size_t)(row0 + row) * H + cp);
        if (sScale) { float s = sScale[row]; v.x *= s; v.y *= s; }
        uint32_t wh, wl; split_pair(v.x, v.y, wh, wl);
        uint32_t b = (uint32_t)row * ROWB + cp * 2;
        *(uint32_t*)(smc + off + b) = wh;
        *(uint32_t*)(smc + off + LOOFF + b) = wl;
    }
}
__device__ __forceinline__ void copy_wimg(char* smc, int chunk, int tid) {
    const uint2* sh = (const uint2*)(g_wimg_hi + (size_t)chunk * 128 * ASTRIDE);
    const uint2* sl = (const uint2*)(g_wimg_lo + (size_t)chunk * 128 * ASTRIDE);
    uint2* dh = (uint2*)(smc + OFF_B);
    uint2* dl = (uint2*)(smc + OFF_B + LOOFF);
#pragma unroll
    for (int j = 0; j < 17; j++) {
        dh[tid + j * 256] = sh[tid + j * 256];
        dl[tid + j * 256] = sl[tid + j * 256];
    }
}

// store acc (+bias, optional relu) as split bf16 into sA
__device__ __forceinline__ void store_acc_split(char* smc, float acc[2][8][4],
                                                const float* __restrict__ bias, int relu,
                                                int mrow, int ncol, int lane) {
#pragma unroll
    for (int i = 0; i < 2; i++)
#pragma unroll
        for (int q2 = 0; q2 < 2; q2++) {
            int row = mrow + i * 16 + q2 * 8 + (lane >> 2);
#pragma unroll
            for (int j = 0; j < 8; j++) {
                int c = ncol + j * 8 + (lane & 3) * 2;
                float v0 = acc[i][j][q2 * 2]     + __ldg(bias + c);
                float v1 = acc[i][j][q2 * 2 + 1] + __ldg(bias + c + 1);
                if (relu) { v0 = fmaxf(v0, 0.f); v1 = fmaxf(v1, 0.f); }
                uint32_t wh, wl; split_pair(v0, v1, wh, wl);
                uint32_t b = (uint32_t)row * ROWB + c * 2;
                *(uint32_t*)(smc + OFF_A + b) = wh;
                *(uint32_t*)(smc + OFF_A + LOOFF + b) = wl;
            }
        }
}

// ---------------- shared tail: MLP2 + GRU + epilogue ----------------
__device__ __forceinline__ void tail_model(char* smc, uint32_t smb, int cb0,
    float acc[2][8][4],
    const float* __restrict__ b1, const float* __restrict__ b2,
    const float* __restrict__ bih, const float* __restrict__ bhh,
    float* __restrict__ outp, float* __restrict__ scat, const int* sScat,
    int row0, int nrows, int tid)
{
    const int wid = tid >> 5, lane = tid & 31;
    const int mrow = (wid & 3) * 32, ncol = (wid >> 2) * 64;
    const uint32_t aA = smb + OFF_A + mrow * ROWB;
    const uint32_t aO = smb + OFF_OLD + mrow * ROWB;
    const uint32_t bB = smb + OFF_B + ncol * ROWB;
    float rn[2][8][4];

    // 1. h1 = relu(acc + b1) -> sA ; acc = h1 @ w2^T
    store_acc_split(smc, acc, b1, 1, mrow, ncol, lane);
    copy_wimg(smc, cb0 + 0, tid);
    __syncthreads();
    ZACC(acc);
    gemm128(aA, bB, acc, lane);
    __syncthreads();

    // 2. e_out = acc + b2 -> sA ; acc = e_out @ wih_r
    store_acc_split(smc, acc, b2, 0, mrow, ncol, lane);
    copy_wimg(smc, cb0 + 1, tid);
    __syncthreads();
    ZACC(acc);
    gemm128(aA, bB, acc, lane);
    __syncthreads();

    // 3. acc += old @ whh_r  -> r
    copy_wimg(smc, cb0 + 4, tid);
    __syncthreads();
    gemm128(aO, bB, acc, lane);
    __syncthreads();
#pragma unroll
    for (int i = 0; i < 2; i++)
#pragma unroll
        for (int j = 0; j < 8; j++)
#pragma unroll
            for (int q = 0; q < 4; q++) {
                int c = ncol + j * 8 + (lane & 3) * 2 + (q & 1);
                rn[i][j][q] = sigm(acc[i][j][q] + __ldg(bih + c) + __ldg(bhh + c));
            }

    // 4. acc = old @ whh_n -> hg ; acc = r*(hg + bhh_n)
    copy_wimg(smc, cb0 + 6, tid);
    __syncthreads();
    ZACC(acc);
    gemm128(aO, bB, acc, lane);
    __syncthreads();
#pragma unroll
    for (int i = 0; i < 2; i++)
#pragma unroll
        for (int j = 0; j < 8; j++)
#pragma unroll
            for (int q = 0; q < 4; q++) {
                int c = ncol + j * 8 + (lane & 3) * 2 + (q & 1);
                acc[i][j][q] = rn[i][j][q] * (acc[i][j][q] + __ldg(bhh + 2 * H + c));
            }

    // 5. acc += e_out @ wih_n -> n = tanh(acc + bih_n)
    copy_wimg(smc, cb0 + 3, tid);
    __syncthreads();
    gemm128(aA, bB, acc, lane);
    __syncthreads();
#pragma unroll
    for (int i = 0; i < 2; i++)
#pragma unroll
        for (int j = 0; j < 8; j++)
#pragma unroll
            for (int q = 0; q < 4; q++) {
                int c = ncol + j * 8 + (lane & 3) * 2 + (q & 1);
                rn[i][j][q] = ftanh(acc[i][j][q] + __ldg(bih + 2 * H + c));
            }

    // 6. acc = e_out @ wih_z + old @ whh_z -> z
    copy_wimg(smc, cb0 + 2, tid);
    __syncthreads();
    ZACC(acc);
    gemm128(aA, bB, acc, lane);
    __syncthreads();
    copy_wimg(smc, cb0 + 5, tid);
    __syncthreads();
    gemm128(aO, bB, acc, lane);

    // 7. epilogue
#pragma unroll
    for (int i = 0; i < 2; i++)
#pragma unroll
        for (int q2 = 0; q2 < 2; q2++) {
            int row = mrow + i * 16 + q2 * 8 + (lane >> 2);
            int gr = row0 + row;
            if (gr >= nrows) continue;
            int sidx = sScat[row];
#pragma unroll
            for (int j = 0; j < 8; j++) {
                int c = ncol + j * 8 + (lane & 3) * 2;
                uint32_t b = (uint32_t)row * ROWB + c * 2;
                union { uint32_t u; __nv_bfloat162 v; } th, tl;
                th.u = *(uint32_t*)(smc + OFF_OLD + b);
                tl.u = *(uint32_t*)(smc + OFF_OLD + LOOFF + b);
                float hold0 = __bfloat162float(th.v.x) + __bfloat162float(tl.v.x);
                float hold1 = __bfloat162float(th.v.y) + __bfloat162float(tl.v.y);
                float h[2];
#pragma unroll
                for (int e = 0; e < 2; e++) {
                    int col = c + e, q = q2 * 2 + e;
                    float z = sigm(acc[i][j][q] + __ldg(bih + H + col) + __ldg(bhh + H + col));
                    h[e] = (1.f - z) * rn[i][j][q] + z * (e ? hold1 : hold0);
                }
                *(float2*)(outp + (size_t)gr * H + c) = make_float2(h[0], h[1]);
                atomicAdd(scat + (size_t)sidx * H + c, h[0]);
                atomicAdd(scat + (size_t)sidx * H + c + 1, h[1]);
            }
        }
}

// ---------------- weight prep: fp32 -> split bf16 padded row-major images ----------------
__global__ void k_prep(const float* ew1, const float* ew2, const float* ewih, const float* ewhh,
                       const float* nw1, const float* nw2, const float* nwih, const float* nwhh) {
    int c = blockIdx.x;
    const float* src; int ldw;
    if (c < 4)        { src = ew1 + c * 128;               ldw = 512; }
    else if (c == 4)  { src = ew2;                         ldw = 128; }
    else if (c < 8)   { src = ewih + (c - 5) * 128 * 128;  ldw = 128; }
    else if (c < 11)  { src = ewhh + (c - 8) * 128 * 128;  ldw = 128; }
    else if (c < 14)  { src = nw1 + (c - 11) * 128;        ldw = 384; }
    else if (c == 14) { src = nw2;                         ldw = 128; }
    else if (c < 18)  { src = nwih + (c - 15) * 128 * 128; ldw = 128; }
    else              { src = nwhh + (c - 18) * 128 * 128; ldw = 128; }
    __nv_bfloat16* dh = g_wimg_hi + (size_t)c * 128 * ASTRIDE;
    __nv_bfloat16* dl = g_wimg_lo + (size_t)c * 128 * ASTRIDE;
    for (int j = 0; j < 32; j++) {
        int p = threadIdx.x + j * 256;
        int row = p >> 6, cp = (p & 63) * 2;
        float2 v = *(const float2*)(src + (size_t)row * ldw + cp);
        uint32_t wh, wl; split_pair(v.x, v.y, wh, wl);
        *(uint32_t*)((char*)dh + (size_t)row * ROWB + cp * 2) = wh;
        *(uint32_t*)((char*)dl + (size_t)row * ROWB + cp * 2) = wl;
    }
}

// ---------------- edge kernel ----------------
__global__ __launch_bounds__(256, 1) void k_edge(
    const float* __restrict__ x, const float* __restrict__ eain, float* __restrict__ eaout,
    const float* __restrict__ u,
    const int* __restrict__ src, const int* __restrict__ dst, const int* __restrict__ batch,
    const float* __restrict__ b1, const float* __restrict__ b2,
    const float* __restrict__ bih, const float* __restrict__ bhh,
    float* __restrict__ aggSum, int E)
{
    extern __shared__ char smc[];
    uint32_t smb = smem_u32(smc);
    int tid = threadIdx.x, wid = tid >> 5, lane = tid & 31;
    int row0 = blockIdx.x * 128;
    int mrow = (wid & 3) * 32, ncol = (wid >> 2) * 64;
    int* sSrc = (int*)(smc + OFF_IDX);
    int* sDst = sSrc + 128;
    int* sBat = sDst + 128;

    if (tid < 128) {
        int e = row0 + tid;
        int s = 0, d = 0;
        if (e < E) { s = src[e]; d = dst[e]; }
        sSrc[tid] = s; sDst[tid] = d; sBat[tid] = batch[s];
    }
    fill_direct(smc, OFF_OLD, eain, tid, row0, E, 0);
    __syncthreads();

    const uint32_t aA = smb + OFF_A + mrow * ROWB;
    const uint32_t aO = smb + OFF_OLD + mrow * ROWB;
    const uint32_t bB = smb + OFF_B + ncol * ROWB;
    float acc[2][8][4];
    ZACC(acc);

    fill_gather(smc, OFF_A, x, sSrc, tid);
    copy_wimg(smc, 0, tid);
    __syncthreads();
    gemm128(aA, bB, acc, lane);
    __syncthreads();

    fill_gather(smc, OFF_A, x, sDst, tid);
    copy_wimg(smc, 1, tid);
    __syncthreads();
    gemm128(aA, bB, acc, lane);
    __syncthreads();

    copy_wimg(smc, 2, tid);
    __syncthreads();
    gemm128(aO, bB, acc, lane);
    __syncthreads();

    fill_gather(smc, OFF_A, u, sBat, tid);
    copy_wimg(smc, 3, tid);
    __syncthreads();
    gemm128(aA, bB, acc, lane);
    __syncthreads();

    tail_model(smc, smb, 4, acc, b1, b2, bih, bhh, eaout, aggSum, sDst, row0, E, tid);
}

// ---------------- node kernel ----------------
__global__ __launch_bounds__(256, 1) void k_node(
    const float* __restrict__ xin, float* __restrict__ xout,
    const float* __restrict__ u, const int* __restrict__ batch,
    const float* __restrict__ aggSum, const float* __restrict__ invE,
    const float* __restrict__ b1, const float* __restrict__ b2,
    const float* __restrict__ bih, const float* __restrict__ bhh,
    float* __restrict__ graphSum, int N)
{
    extern __shared__ char smc[];
    uint32_t smb = smem_u32(smc);
    int tid = threadIdx.x, wid = tid >> 5, lane = tid & 31;
    int row0 = blockIdx.x * 128;
    int mrow = (wid & 3) * 32, ncol = (wid >> 2) * 64;
    int* sBat = (int*)(smc + OFF_IDX);
    float* sInv = (float*)(sBat + 128);

    if (tid < 128) {
        int n = row0 + tid;
        int bb = 0; float iv = 0.f;
        if (n < N) { bb = batch[n]; iv = invE[n]; }
        sBat[tid] = bb; sInv[tid] = iv;
    }
    fill_direct(smc, OFF_OLD, xin, tid, row0, N, 0);
    __syncthreads();

    const uint32_t aA = smb + OFF_A + mrow * ROWB;
    const uint32_t aO = smb + OFF_OLD + mrow * ROWB;
    const uint32_t bB = smb + OFF_B + ncol * ROWB;
    float acc[2][8][4];
    ZACC(acc);

    copy_wimg(smc, 11, tid);
    __syncthreads();
    gemm128(aO, bB, acc, lane);
    __syncthreads();

    fill_direct(smc, OFF_A, aggSum, tid, row0, N, sInv);
    copy_wimg(smc, 12, tid);
    __syncthreads();
    gemm128(aA, bB, acc, lane);
    __syncthreads();

    fill_gather(smc, OFF_A, u, sBat, tid);
    copy_wimg(smc, 13, tid);
    __syncthreads();
    gemm128(aA, bB, acc, lane);
    __syncthreads();

    tail_model(smc, smb, 14, acc, b1, b2, bih, bhh, xout, graphSum, sBat, row0, N, tid);
}

// ---------------- utility + global kernels ----------------
__global__ void k_zero(float* p, int n) {
    int i = blockIdx.x * blockDim.x + threadIdx.x, s = gridDim.x * blockDim.x;
    for (; i < n; i += s) p[i] = 0.f;
}
__global__ void k_count(const int* __restrict__ idx, int n, float* cnt) {
    int i = blockIdx.x * blockDim.x + threadIdx.x, s = gridDim.x * blockDim.x;
    for (; i < n; i += s) atomicAdd(&cnt[idx[i]], 1.f);
}
__global__ void k_invert(float* c, int n) {
    int i = blockIdx.x * blockDim.x + threadIdx.x;
    if (i < n) c[i] = 1.f / fmaxf(c[i], 1.f);
}
__device__ __forceinline__ float dot128(const float* __restrict__ w, const float* v) {
    float s0 = 0, s1 = 0;
#pragma unroll 16
    for (int k = 0; k < H; k += 2) { s0 = fmaf(w[k], v[k], s0); s1 = fmaf(w[k + 1], v[k + 1], s1); }
    return s0 + s1;
}
__global__ __launch_bounds__(128) void k_global(
    const float* __restrict__ uin, float* __restrict__ uout,
    const float* __restrict__ graphSum, const float* __restrict__ invB,
    const float* __restrict__ w1, const float* __restrict__ b1,
    const float* __restrict__ w2, const float* __restrict__ b2,
    const float* __restrict__ wih, const float* __restrict__ whh,
    const float* __restrict__ bih, const float* __restrict__ bhh,
    float* __restrict__ out, int step)
{
    __shared__ float gin[2 * H], h1[H], eo[H];
    int b = blockIdx.x, t = threadIdx.x;
    float uold = uin[b * H + t];
    gin[t] = uold;
    gin[H + t] = graphSum[b * H + t] * invB[b];
    __syncthreads();
    {
        float s0 = 0, s1 = 0;
        const float* wr = w1 + t * 2 * H;
#pragma unroll 16
        for (int k = 0; k < 2 * H; k += 2) { s0 = fmaf(wr[k], gin[k], s0); s1 = fmaf(wr[k + 1], gin[k + 1], s1); }
        h1[t] = fmaxf(s0 + s1 + b1[t], 0.f);
    }
    __syncthreads();
    eo[t] = dot128(w2 + t * H, h1) + b2[t];
    __syncthreads();
    float r = sigm(dot128(wih + t * H, eo) + bih[t] + dot128(whh + t * H, gin) + bhh[t]);
    float z = sigm(dot128(wih + (H + t) * H, eo) + bih[H + t] + dot128(whh + (H + t) * H, gin) + bhh[H + t]);
    float n = tanhf(dot128(wih + (2 * H + t) * H, eo) + bih[2 * H + t]
                    + r * (dot128(whh + (2 * H + t) * H, gin) + bhh[2 * H + t]));
    float hn = (1.f - z) * n + z * uold;
    uout[b * H + t] = hn;
    out[(b * STEPS + step) * H + t] = hn;
}

// ---------------- launch ----------------
extern "C" void kernel_launch(void* const* d_in, const int* in_sizes, int n_in,
                              void* d_out, int out_size) {
    const float* x = (const float*)d_in[0];
    const int* ei = (const int*)d_in[1];
    const float* ea = (const float*)d_in[2];
    const float* u = (const float*)d_in[3];
    const int* batch = (const int*)d_in[4];
    const float* ew1 = (const float*)d_in[5],  *eb1 = (const float*)d_in[6];
    const float* ew2 = (const float*)d_in[7],  *eb2 = (const float*)d_in[8];
    const float* nw1 = (const float*)d_in[9],  *nb1 = (const float*)d_in[10];
    const float* nw2 = (const float*)d_in[11], *nb2 = (const float*)d_in[12];
    const float* gw1 = (const float*)d_in[13], *gb1 = (const float*)d_in[14];
    const float* gw2 = (const float*)d_in[15], *gb2 = (const float*)d_in[16];
    const float* ewih = (const float*)d_in[17], *ewhh = (const float*)d_in[18];
    const float* ebih = (const float*)d_in[19], *ebhh = (const float*)d_in[20];
    const float* nwih = (const float*)d_in[21], *nwhh = (const float*)d_in[22];
    const float* nbih = (const float*)d_in[23], *nbhh = (const float*)d_in[24];
    const float* gwih = (const float*)d_in[25], *gwhh = (const float*)d_in[26];
    const float* gbih = (const float*)d_in[27], *gbhh = (const float*)d_in[28];
    float* out = (float*)d_out;

    const int E = in_sizes[1] / 2, N = in_sizes[0] / H, B = in_sizes[3] / H;

    float *edgeBuf, *xBuf, *uBuf, *aggSum, *graphSum, *cntE, *cntB;
    cudaGetSymbolAddress((void**)&edgeBuf, g_edge);
    cudaGetSymbolAddress((void**)&xBuf, g_x);
    cudaGetSymbolAddress((void**)&uBuf, g_u);
    cudaGetSymbolAddress((void**)&aggSum, g_aggSum);
    cudaGetSymbolAddress((void**)&graphSum, g_graphSum);
    cudaGetSymbolAddress((void**)&cntE, g_cntE);
    cudaGetSymbolAddress((void**)&cntB, g_cntB);

    const int* src = ei;
    const int* dst = ei + E;

    cudaFuncSetAttribute(k_edge, cudaFuncAttributeMaxDynamicSharedMemorySize, SMEM_BYTES);
    cudaFuncSetAttribute(k_node, cudaFuncAttributeMaxDynamicSharedMemorySize, SMEM_BYTES);

    k_prep<<<21, 256>>>(ew1, ew2, ewih, ewhh, nw1, nw2, nwih, nwhh);

    k_zero<<<(N + 255) / 256, 256>>>(cntE, N);
    k_zero<<<1, 64>>>(cntB, B);
    k_count<<<512, 256>>>(dst, E, cntE);
    k_count<<<128, 256>>>(batch, N, cntB);
    k_invert<<<(N + 255) / 256, 256>>>(cntE, N);
    k_invert<<<1, 64>>>(cntB, B);

    for (int step = 0; step < STEPS; step++) {
        k_zero<<<4096, 256>>>(aggSum, N * H);
        k_zero<<<32, 256>>>(graphSum, B * H);

        const float* xin = (step == 0) ? x : xBuf;
        const float* eain = (step == 0) ? ea : edgeBuf;
        const float* uin = (step == 0) ? u : uBuf;

        k_edge<<<(E + 127) / 128, 256, SMEM_BYTES>>>(
            xin, eain, edgeBuf, uin, src, dst, batch,
            eb1, eb2, ebih, ebhh, aggSum, E);

        k_node<<<(N + 127) / 128, 256, SMEM_BYTES>>>(
            xin, xBuf, uin, batch, aggSum, cntE,
            nb1, nb2, nbih, nbhh, graphSum, N);

        k_global<<<B, H>>>(uin, uBuf, graphSum, cntB,
            gw1, gb1, gw2, gb2, gwih, gwhh, gbih, gbhh, out, step);
    }
}